// round 3
// baseline (speedup 1.0000x reference)
#include <cuda_runtime.h>
#include <stdint.h>

// ---------------------------------------------------------------------------
// SSIM loss, (16,3,512,512) fp32. Separable 11x11 Gaussian conv.
// 4 fused channels: (mu1,mu2) and (E[a^2+b^2], E[ab]) as packed f32x2.
// 32x64 tiles, conflict-free smem mapping, single kernel with integer-
// atomic deterministic reduction (last block finalizes + resets).
// ---------------------------------------------------------------------------

#define IMG_H   512
#define IMG_W   512
#define PLANES  48
#define RAD     5
#define TX      32
#define TY      64
#define INW     42            // TX + 10
#define INH     74            // TY + 10
#define INH_A   76            // h arrays padded: phase-3 strip 10 over-reads rows 74,75
#define SW      43            // u64 row stride, s_in/s_sp (odd mod 16 -> conflict-free)
#define HW      33            // u64 row stride, h arrays
#define NT      384
#define NTILES_X 16
#define NTILES_Y 8
#define NBLOCKS (NTILES_X * NTILES_Y * PLANES)   // 6144
#define NPIX    12582912.0
#define FXSCALE 2147483648.0                     // 2^31 fixed-point scale

// 1D Gaussian, sigma=1.5, normalized.
__device__ __constant__ const float W11_c[11] = {
    0.00102838f, 0.00759876f, 0.03600077f, 0.10936071f, 0.21300554f,
    0.26601172f,
    0.21300554f, 0.10936071f, 0.03600077f, 0.00759876f, 0.00102838f
};

__device__ unsigned long long g_acc;   // zero-init at module load; reset by finalizer
__device__ unsigned int       g_cnt;

// ---------- f32x2 packed helpers ----------
__device__ __forceinline__ unsigned long long pack2(float lo, float hi) {
    unsigned long long r;
    asm("mov.b64 %0, {%1, %2};" : "=l"(r) : "f"(lo), "f"(hi));
    return r;
}
__device__ __forceinline__ void unpack2(unsigned long long v, float &lo, float &hi) {
    asm("mov.b64 {%0, %1}, %2;" : "=f"(lo), "=f"(hi) : "l"(v));
}
__device__ __forceinline__ unsigned long long fma2(unsigned long long a,
                                                   unsigned long long b,
                                                   unsigned long long c) {
    unsigned long long d;
    asm("fma.rn.f32x2 %0, %1, %2, %3;" : "=l"(d) : "l"(a), "l"(b), "l"(c));
    return d;
}

__global__ void __launch_bounds__(NT, 2)
ssim_main(const float *__restrict__ img1, const float *__restrict__ img2,
          float *__restrict__ out) {
    extern __shared__ unsigned long long sm[];
    unsigned long long *s_in  = sm;                       // INH*SW  (a,b)
    unsigned long long *s_sp  = s_in  + INH * SW;         // INH*SW  (a^2+b^2, a*b)
    unsigned long long *s_hmu = s_sp  + INH * SW;         // INH_A*HW (mu1,mu2) h-conv
    unsigned long long *s_hse = s_hmu + INH_A * HW;       // INH_A*HW (Ess,E12) h-conv
    __shared__ float s_red[NT / 32];

    const int tid   = threadIdx.x;
    const int plane = blockIdx.z;
    const size_t base = (size_t)plane * (IMG_H * IMG_W);
    const int x0 = blockIdx.x * TX - RAD;
    const int y0 = blockIdx.y * TY - RAD;

    // zero the two pad rows of h arrays (read by strip 10, contributions predicated)
    if (tid < 2 * HW) {
        s_hmu[INH * HW + tid] = 0ULL;
        s_hse[INH * HW + tid] = 0ULL;
    }

    // ---------------- phase 1: load tile+halo, precompute (ss, p) ----------
    for (int i = tid; i < INH * INW; i += NT) {
        const int r = i / INW;
        const int c = i - r * INW;
        const int gx = x0 + c;
        const int gy = y0 + r;
        float a = 0.0f, b = 0.0f;
        if ((unsigned)gx < (unsigned)IMG_W && (unsigned)gy < (unsigned)IMG_H) {
            const size_t off = base + (size_t)gy * IMG_W + gx;
            a = img1[off];
            b = img2[off];
        }
        s_in[r * SW + c] = pack2(a, b);
        s_sp[r * SW + c] = pack2(a * a + b * b, a * b);
    }
    __syncthreads();

    unsigned long long wp[11];
#pragma unroll
    for (int k = 0; k < 11; k++) wp[k] = pack2(W11_c[k], W11_c[k]);

    // ---------------- phase 2: horizontal conv, 8 outputs per item ---------
    // item = g*INH + r  (consecutive lanes -> consecutive rows: stride 43 u64
    // is odd mod 16 -> conflict-free LDS.64)
    if (tid < INH * 4) {
        const int g  = tid / INH;
        const int r  = tid - g * INH;
        const int c0 = g * 8;
        const unsigned long long *pin = s_in + r * SW + c0;
        const unsigned long long *psp = s_sp + r * SW + c0;
        unsigned long long mu[8], se[8];
#pragma unroll
        for (int o = 0; o < 8; o++) { mu[o] = 0ULL; se[o] = 0ULL; }
#pragma unroll
        for (int j = 0; j < 18; j++) {
            const unsigned long long v  = pin[j];
            const unsigned long long sp = psp[j];
#pragma unroll
            for (int o = 0; o < 8; o++) {
                const int k = j - o;
                if (k >= 0 && k < 11) {
                    mu[o] = fma2(wp[k], v,  mu[o]);
                    se[o] = fma2(wp[k], sp, se[o]);
                }
            }
        }
#pragma unroll
        for (int o = 0; o < 8; o++) {
            s_hmu[r * HW + c0 + o] = mu[o];
            s_hse[r * HW + c0 + o] = se[o];
        }
    }
    __syncthreads();

    // ---------------- phase 3: vertical conv + SSIM, 6-row strips ----------
    float tsum = 0.0f;
    {
        const int w   = tid >> 5;
        const int col = tid & 31;
        if (w < 11) {                       // strips cover rows 0..65; 64,65 predicated
            const int ry0 = w * 6;
            const unsigned long long *pm = s_hmu + ry0 * HW + col;
            const unsigned long long *ps = s_hse + ry0 * HW + col;
            unsigned long long amu[6], ase[6];
#pragma unroll
            for (int o = 0; o < 6; o++) { amu[o] = 0ULL; ase[o] = 0ULL; }
#pragma unroll
            for (int jj = 0; jj < 16; jj++) {
                const unsigned long long m  = pm[jj * HW];
                const unsigned long long s2 = ps[jj * HW];
#pragma unroll
                for (int o = 0; o < 6; o++) {
                    const int k = jj - o;
                    if (k >= 0 && k < 11) {
                        amu[o] = fma2(wp[k], m,  amu[o]);
                        ase[o] = fma2(wp[k], s2, ase[o]);
                    }
                }
            }
            const float C1 = 1e-4f;   // 0.01^2
            const float C2 = 9e-4f;   // 0.03^2
#pragma unroll
            for (int o = 0; o < 6; o++) {
                if (ry0 + o < TY) {
                    float mu1, mu2, ess, e12;
                    unpack2(amu[o], mu1, mu2);
                    unpack2(ase[o], ess, e12);
                    const float m12 = mu1 * mu2;
                    const float m11 = mu1 * mu1;
                    const float m22 = mu2 * mu2;
                    const float s12 = e12 - m12;
                    const float num = (2.0f * m12 + C1) * (2.0f * s12 + C2);
                    const float den = (m11 + m22 + C1) * (ess - m11 - m22 + C2);
                    tsum += __fdividef(num, den);
                }
            }
        }
    }

    // ---------------- deterministic reduction -----------------------------
#pragma unroll
    for (int off = 16; off > 0; off >>= 1)
        tsum += __shfl_down_sync(0xffffffffu, tsum, off);
    if ((tid & 31) == 0) s_red[tid >> 5] = tsum;
    __syncthreads();
    if (tid == 0) {
        double bs = 0.0;
#pragma unroll
        for (int i = 0; i < NT / 32; i++) bs += (double)s_red[i];
        const unsigned long long q =
            (unsigned long long)__double2ll_rn(bs * FXSCALE);
        atomicAdd(&g_acc, q);
        __threadfence();
        const unsigned int done = atomicAdd(&g_cnt, 1u);
        if (done == NBLOCKS - 1) {
            const unsigned long long tot = atomicAdd(&g_acc, 0ULL);
            const double mean = ((double)(long long)tot / FXSCALE) / NPIX;
            out[0] = (float)(1.0 - mean);
            g_acc = 0ULL;        // reset for next graph replay
            g_cnt = 0u;
            __threadfence();
        }
    }
}

extern "C" void kernel_launch(void *const *d_in, const int *in_sizes, int n_in,
                              void *d_out, int out_size) {
    (void)in_sizes; (void)n_in; (void)out_size;
    const float *img1 = (const float *)d_in[0];
    const float *img2 = (const float *)d_in[1];
    float *out = (float *)d_out;

    static const int SMEM_BYTES =
        (int)((2 * INH * SW + 2 * INH_A * HW) * sizeof(unsigned long long)); // 91040
    cudaFuncSetAttribute(ssim_main, cudaFuncAttributeMaxDynamicSharedMemorySize,
                         SMEM_BYTES);

    dim3 grid(NTILES_X, NTILES_Y, PLANES);
    ssim_main<<<grid, NT, SMEM_BYTES>>>(img1, img2, out);
}

// round 4
// speedup vs baseline: 1.1594x; 1.1594x over previous
#include <cuda_runtime.h>
#include <stdint.h>

// ---------------------------------------------------------------------------
// SSIM loss, (16,3,512,512) fp32. Separable 11x11 Gaussian conv.
// 4 channels per pixel packed in one ulonglong2: (a,b) | (a^2+b^2, a*b).
// 32x32 tiles, 256 threads, LDS.128 everywhere, 4 CTAs/SM, single kernel
// with order-independent fixed-point atomic reduction.
// ---------------------------------------------------------------------------

#define IMG_H   512
#define IMG_W   512
#define PLANES  48
#define RAD     5
#define TX      32
#define TY      32
#define INW     42
#define INH     42
#define SW      43            // ulonglong2 row stride, s_in (conflict-free LDS.128)
#define HW      33            // ulonglong2 row stride, h array
#define NT      256
#define NTILES_X 16
#define NTILES_Y 16
#define NBLOCKS (NTILES_X * NTILES_Y * PLANES)   // 12288
#define NPIX    12582912.0
#define FXSCALE 2147483648.0                     // 2^31

// 1D Gaussian, sigma=1.5, normalized.
__device__ __constant__ const float W11_c[11] = {
    0.00102838f, 0.00759876f, 0.03600077f, 0.10936071f, 0.21300554f,
    0.26601172f,
    0.21300554f, 0.10936071f, 0.03600077f, 0.00759876f, 0.00102838f
};

__device__ unsigned long long g_acc;   // zero at load; finalizer resets
__device__ unsigned int       g_cnt;

// ---------- f32x2 packed helpers ----------
__device__ __forceinline__ unsigned long long pack2(float lo, float hi) {
    unsigned long long r;
    asm("mov.b64 %0, {%1, %2};" : "=l"(r) : "f"(lo), "f"(hi));
    return r;
}
__device__ __forceinline__ void unpack2(unsigned long long v, float &lo, float &hi) {
    asm("mov.b64 {%0, %1}, %2;" : "=f"(lo), "=f"(hi) : "l"(v));
}
__device__ __forceinline__ unsigned long long fma2(unsigned long long a,
                                                   unsigned long long b,
                                                   unsigned long long c) {
    unsigned long long d;
    asm("fma.rn.f32x2 %0, %1, %2, %3;" : "=l"(d) : "l"(a), "l"(b), "l"(c));
    return d;
}

// symmetric weight accessor (k is compile-time in unrolled loops)
#define WQ(k) wp[(k) < 6 ? (k) : 10 - (k)]

// Horizontal conv for G consecutive output columns of one row.
template <int G>
__device__ __forceinline__ void hconv_group(
    const ulonglong2 *__restrict__ pin,      // &s_in[r*SW + c0]
    ulonglong2 *__restrict__ pout,           // &s_h[r*HW + c0]
    const unsigned long long *__restrict__ wp) {
    unsigned long long mu[G], se[G];
#pragma unroll
    for (int o = 0; o < G; o++) { mu[o] = 0ULL; se[o] = 0ULL; }
#pragma unroll
    for (int j = 0; j < G + 10; j++) {
        const ulonglong2 v = pin[j];
#pragma unroll
        for (int o = 0; o < G; o++) {
            const int k = j - o;
            if (k >= 0 && k < 11) {
                mu[o] = fma2(WQ(k), v.x, mu[o]);
                se[o] = fma2(WQ(k), v.y, se[o]);
            }
        }
    }
#pragma unroll
    for (int o = 0; o < G; o++)
        pout[o] = make_ulonglong2(mu[o], se[o]);
}

__global__ void __launch_bounds__(NT, 4)
ssim_main(const float *__restrict__ img1, const float *__restrict__ img2,
          float *__restrict__ out) {
    extern __shared__ ulonglong2 sm[];
    ulonglong2 *s_in = sm;                 // INH*SW  : (a,b)|(ss,p)
    ulonglong2 *s_h  = s_in + INH * SW;    // INH*HW  : (mu1,mu2)|(Ess,E12)
    __shared__ float s_red[NT / 32];

    const int tid   = threadIdx.x;
    const size_t base = (size_t)blockIdx.z * (IMG_H * IMG_W);
    const int x0 = blockIdx.x * TX - RAD;
    const int y0 = blockIdx.y * TY - RAD;

    // ---------------- phase 1: load tile+halo, build 4-channel pack --------
    for (int i = tid; i < INH * INW; i += NT) {
        const int r = i / INW;
        const int c = i - r * INW;
        const int gx = x0 + c;
        const int gy = y0 + r;
        float a = 0.0f, b = 0.0f;
        if ((unsigned)gx < (unsigned)IMG_W && (unsigned)gy < (unsigned)IMG_H) {
            const size_t off = base + (size_t)gy * IMG_W + gx;
            a = img1[off];
            b = img2[off];
        }
        const float ss = fmaf(a, a, b * b);
        const float p  = a * b;
        s_in[r * SW + c] = make_ulonglong2(pack2(a, b), pack2(ss, p));
    }
    __syncthreads();

    unsigned long long wp[6];
#pragma unroll
    for (int k = 0; k < 6; k++) wp[k] = pack2(W11_c[k], W11_c[k]);

    // ---------------- phase 2: horizontal conv -----------------------------
    // 252 items: 42 rows x 6 col-groups of {6,6,5,5,5,5} outputs.
    // consecutive threads -> consecutive rows: stride 43*16B, conflict-free.
    if (tid < 252) {
        const int r = tid % 42;
        const int g = tid / 42;
        if (g < 2) {
            const int c0 = g * 6;
            hconv_group<6>(s_in + r * SW + c0, s_h + r * HW + c0, wp);
        } else {
            const int c0 = 12 + (g - 2) * 5;
            hconv_group<5>(s_in + r * SW + c0, s_h + r * HW + c0, wp);
        }
    }
    __syncthreads();

    // ---------------- phase 3: vertical conv + SSIM ------------------------
    // 256 items: 32 cols x 8 strips of 4 rows. Lanes walk columns (16B
    // stride) -> conflict-free regardless of row stride. Rows 0..41 exactly.
    float tsum = 0.0f;
    {
        const int col = tid & 31;
        const int ry0 = (tid >> 5) * 4;
        const ulonglong2 *ph = s_h + ry0 * HW + col;
        unsigned long long amu[4], ase[4];
#pragma unroll
        for (int o = 0; o < 4; o++) { amu[o] = 0ULL; ase[o] = 0ULL; }
#pragma unroll
        for (int jj = 0; jj < 14; jj++) {
            const ulonglong2 v = ph[jj * HW];
#pragma unroll
            for (int o = 0; o < 4; o++) {
                const int k = jj - o;
                if (k >= 0 && k < 11) {
                    amu[o] = fma2(WQ(k), v.x, amu[o]);
                    ase[o] = fma2(WQ(k), v.y, ase[o]);
                }
            }
        }
        const float C1 = 1e-4f;   // 0.01^2
        const float C2 = 9e-4f;   // 0.03^2
#pragma unroll
        for (int o = 0; o < 4; o++) {
            float mu1, mu2, ess, e12;
            unpack2(amu[o], mu1, mu2);
            unpack2(ase[o], ess, e12);
            const float m12 = mu1 * mu2;
            const float m11 = mu1 * mu1;
            const float m22 = mu2 * mu2;
            const float s12 = e12 - m12;
            const float num = (2.0f * m12 + C1) * (2.0f * s12 + C2);
            const float den = (m11 + m22 + C1) * (ess - m11 - m22 + C2);
            tsum += __fdividef(num, den);
        }
    }

    // ---------------- deterministic reduction ------------------------------
#pragma unroll
    for (int off = 16; off > 0; off >>= 1)
        tsum += __shfl_down_sync(0xffffffffu, tsum, off);
    if ((tid & 31) == 0) s_red[tid >> 5] = tsum;
    __syncthreads();
    if (tid == 0) {
        double bs = 0.0;
#pragma unroll
        for (int i = 0; i < NT / 32; i++) bs += (double)s_red[i];
        const unsigned long long q =
            (unsigned long long)__double2ll_rn(bs * FXSCALE);
        atomicAdd(&g_acc, q);
        __threadfence();
        const unsigned int done = atomicAdd(&g_cnt, 1u);
        if (done == NBLOCKS - 1) {
            const unsigned long long tot = atomicAdd(&g_acc, 0ULL);
            const double mean = ((double)(long long)tot / FXSCALE) / NPIX;
            out[0] = (float)(1.0 - mean);
            g_acc = 0ULL;        // reset for next graph replay
            g_cnt = 0u;
            __threadfence();
        }
    }
}

extern "C" void kernel_launch(void *const *d_in, const int *in_sizes, int n_in,
                              void *d_out, int out_size) {
    (void)in_sizes; (void)n_in; (void)out_size;
    const float *img1 = (const float *)d_in[0];
    const float *img2 = (const float *)d_in[1];
    float *out = (float *)d_out;

    static const int SMEM_BYTES =
        (int)((INH * SW + INH * HW) * sizeof(ulonglong2));   // 51072
    cudaFuncSetAttribute(ssim_main, cudaFuncAttributeMaxDynamicSharedMemorySize,
                         SMEM_BYTES);

    dim3 grid(NTILES_X, NTILES_Y, PLANES);
    ssim_main<<<grid, NT, SMEM_BYTES>>>(img1, img2, out);
}

// round 5
// speedup vs baseline: 1.8605x; 1.6047x over previous
#include <cuda_runtime.h>
#include <stdint.h>

// ---------------------------------------------------------------------------
// SSIM loss, (16,3,512,512) fp32. Separable 11x11 Gaussian.
// Phase A: VERTICAL conv first, registers, straight from global (coalesced),
//          42 cols x 54 rows of v-results -> smem (only intermediate).
// Phase B: horizontal conv + SSIM from smem, LDS.128 conflict-free.
// 4 channels packed in ulonglong2: (mu1,mu2)|(Ess,E12) via fma.rn.f32x2.
// Single kernel; order-independent fixed-point atomic reduction.
// ---------------------------------------------------------------------------

#define IMG_H   512
#define IMG_W   512
#define PLANES  48
#define TX      32
#define TY      54
#define RSTRIP  9             // v-conv output rows per Phase-A thread
#define NSTRIPS 6             // 6*9 = 54
#define VCOLS   42            // TX + 10 columns of v-results
#define SVW     43            // ulonglong2 row stride (42 + 1 pad)
#define NT      256
#define NTILES_X 16
#define NTILES_Y 10           // 10*54 = 540 >= 512 (last tile predicated)
#define NBLOCKS (NTILES_X * NTILES_Y * PLANES)   // 7680
#define NPIX    12582912.0
#define FXSCALE 2147483648.0

__device__ __constant__ const float W11_c[11] = {
    0.00102838f, 0.00759876f, 0.03600077f, 0.10936071f, 0.21300554f,
    0.26601172f,
    0.21300554f, 0.10936071f, 0.03600077f, 0.00759876f, 0.00102838f
};

__device__ unsigned long long g_acc;   // zero at load; finalizer resets
__device__ unsigned int       g_cnt;

__device__ __forceinline__ unsigned long long pack2(float lo, float hi) {
    unsigned long long r;
    asm("mov.b64 %0, {%1, %2};" : "=l"(r) : "f"(lo), "f"(hi));
    return r;
}
__device__ __forceinline__ void unpack2(unsigned long long v, float &lo, float &hi) {
    asm("mov.b64 {%0, %1}, %2;" : "=f"(lo), "=f"(hi) : "l"(v));
}
__device__ __forceinline__ unsigned long long fma2(unsigned long long a,
                                                   unsigned long long b,
                                                   unsigned long long c) {
    unsigned long long d;
    asm("fma.rn.f32x2 %0, %1, %2, %3;" : "=l"(d) : "l"(a), "l"(b), "l"(c));
    return d;
}

#define WQ(k) wp[(k) < 6 ? (k) : 10 - (k)]

__global__ void __launch_bounds__(NT, 3)
ssim_main(const float *__restrict__ img1, const float *__restrict__ img2,
          float *__restrict__ out) {
    extern __shared__ ulonglong2 s_v[];          // [TY][SVW] v-conv results
    __shared__ float s_red[NT / 32];

    const int tid = threadIdx.x;
    const size_t base = (size_t)blockIdx.z * (IMG_H * IMG_W);
    const int x0 = blockIdx.x * TX;              // output col origin
    const int y0 = blockIdx.y * TY;              // output row origin

    unsigned long long wp[6];
#pragma unroll
    for (int k = 0; k < 6; k++) wp[k] = pack2(W11_c[k], W11_c[k]);

    // ============ Phase A: vertical conv, global -> regs -> smem ==========
    // thread = (col 0..41, strip 0..5); lanes walk consecutive cols ->
    // coalesced LDG. 9 outputs x 2 packed accumulators = 18 fma chains.
    if (tid < VCOLS * NSTRIPS) {
        const int col = tid % VCOLS;
        const int s   = tid / VCOLS;
        const int gx  = x0 + col - 5;
        const bool xok = (unsigned)gx < (unsigned)IMG_W;
        const int ry0 = s * RSTRIP;

        unsigned long long amu[RSTRIP], ase[RSTRIP];
#pragma unroll
        for (int o = 0; o < RSTRIP; o++) { amu[o] = 0ULL; ase[o] = 0ULL; }

#pragma unroll
        for (int jj = 0; jj < RSTRIP + 10; jj++) {
            const int gy = y0 + ry0 + jj - 5;
            float a = 0.0f, b = 0.0f;
            if (xok && (unsigned)gy < (unsigned)IMG_H) {
                const size_t off = base + (size_t)gy * IMG_W + gx;
                a = img1[off];
                b = img2[off];
            }
            const unsigned long long v  = pack2(a, b);
            const unsigned long long sp = pack2(fmaf(a, a, b * b), a * b);
#pragma unroll
            for (int o = 0; o < RSTRIP; o++) {
                const int k = jj - o;
                if (k >= 0 && k < 11) {
                    amu[o] = fma2(WQ(k), v,  amu[o]);
                    ase[o] = fma2(WQ(k), sp, ase[o]);
                }
            }
        }
#pragma unroll
        for (int o = 0; o < RSTRIP; o++)
            s_v[(ry0 + o) * SVW + col] = make_ulonglong2(amu[o], ase[o]);
    }
    __syncthreads();

    // ============ Phase B: horizontal conv + SSIM =========================
    // thread = (row 0..53, group 0..3 of 8 output cols). Lanes walk rows:
    // stride 43*16B = 172 words = 12 mod 32 -> conflict-free LDS.128.
    float tsum = 0.0f;
    if (tid < TY * 4) {
        const int r  = tid % TY;
        const int g  = tid / TY;
        const int c0 = g * 8;
        const ulonglong2 *pv = s_v + r * SVW + c0;

        unsigned long long amu[8], ase[8];
#pragma unroll
        for (int o = 0; o < 8; o++) { amu[o] = 0ULL; ase[o] = 0ULL; }
#pragma unroll
        for (int j = 0; j < 18; j++) {
            const ulonglong2 v = pv[j];
#pragma unroll
            for (int o = 0; o < 8; o++) {
                const int k = j - o;
                if (k >= 0 && k < 11) {
                    amu[o] = fma2(WQ(k), v.x, amu[o]);
                    ase[o] = fma2(WQ(k), v.y, ase[o]);
                }
            }
        }
        if (y0 + r < IMG_H) {                    // last y-tile predication
            const float C1 = 1e-4f;
            const float C2 = 9e-4f;
#pragma unroll
            for (int o = 0; o < 8; o++) {
                float mu1, mu2, ess, e12;
                unpack2(amu[o], mu1, mu2);
                unpack2(ase[o], ess, e12);
                const float m12 = mu1 * mu2;
                const float m11 = mu1 * mu1;
                const float m22 = mu2 * mu2;
                const float s12 = e12 - m12;
                const float num = (2.0f * m12 + C1) * (2.0f * s12 + C2);
                const float den = (m11 + m22 + C1) * (ess - m11 - m22 + C2);
                tsum += __fdividef(num, den);
            }
        }
    }

    // ============ deterministic reduction =================================
#pragma unroll
    for (int off = 16; off > 0; off >>= 1)
        tsum += __shfl_down_sync(0xffffffffu, tsum, off);
    if ((tid & 31) == 0) s_red[tid >> 5] = tsum;
    __syncthreads();
    if (tid == 0) {
        double bs = 0.0;
#pragma unroll
        for (int i = 0; i < NT / 32; i++) bs += (double)s_red[i];
        const unsigned long long q =
            (unsigned long long)__double2ll_rn(bs * FXSCALE);
        atomicAdd(&g_acc, q);
        __threadfence();
        const unsigned int done = atomicAdd(&g_cnt, 1u);
        if (done == NBLOCKS - 1) {
            const unsigned long long tot = atomicAdd(&g_acc, 0ULL);
            const double mean = ((double)(long long)tot / FXSCALE) / NPIX;
            out[0] = (float)(1.0 - mean);
            g_acc = 0ULL;        // reset for next graph replay
            g_cnt = 0u;
            __threadfence();
        }
    }
}

extern "C" void kernel_launch(void *const *d_in, const int *in_sizes, int n_in,
                              void *d_out, int out_size) {
    (void)in_sizes; (void)n_in; (void)out_size;
    const float *img1 = (const float *)d_in[0];
    const float *img2 = (const float *)d_in[1];
    float *out = (float *)d_out;

    static const int SMEM_BYTES = (int)(TY * SVW * sizeof(ulonglong2)); // 37152
    cudaFuncSetAttribute(ssim_main, cudaFuncAttributeMaxDynamicSharedMemorySize,
                         SMEM_BYTES);

    dim3 grid(NTILES_X, NTILES_Y, PLANES);
    ssim_main<<<grid, NT, SMEM_BYTES>>>(img1, img2, out);
}